// round 8
// baseline (speedup 1.0000x reference)
#include <cuda_runtime.h>
#include <cstdint>

// out[o,m,n] = sum_{kh,j} w0[o,kh,j] * S[m, n+kh, j]       (n >= 1)
// out[o,m,0] = sum_{kh,j} w0[o,kh,j] * S0[m, kh, j]
//   S[m,r,j]  = A[m,r-4,j] + B[m,r-5,j]   (zero-padded in h)
//   S0[m,kh,j]= (kh>=4 ? A[kh-4] : 0) + (kh<=4 ? B[51+kh] : 0)
// Fully fused: each block builds the S slice for its m in smem, then contracts.

__device__ __forceinline__ uint64_t pack2(float s) {
    uint64_t r;
    unsigned u = __float_as_uint(s);
    asm("mov.b64 %0, {%1, %1};" : "=l"(r) : "r"(u));
    return r;
}
__device__ __forceinline__ void ffma2(uint64_t& d, uint64_t a, uint64_t b) {
    asm("fma.rn.f32x2 %0, %1, %2, %0;" : "+l"(d) : "l"(a), "l"(b));
}
__device__ __forceinline__ float2 unpack2(uint64_t v) {
    unsigned lo, hi;
    asm("mov.b64 {%0, %1}, %2;" : "=r"(lo), "=r"(hi) : "l"(v));
    return make_float2(__uint_as_float(lo), __uint_as_float(hi));
}

#define XP 68       // padded x row stride (floats)
#define SJ 81       // Sd row stride (u64)

// grid (56 m, 6 og of 16 o), block 224 = 4 ow × 56 n; each thread 4 o's.
__global__ __launch_bounds__(224, 4)
void fused_kernel(const float* __restrict__ x,
                  const float* __restrict__ w0,
                  const float* __restrict__ w1,
                  float* __restrict__ out)
{
    __shared__ float xp[24 * XP];                      // xp[i][h+5]=x[i,m,h], pads 0
    __shared__ float w1s[24 * 28];
    __shared__ __align__(16) uint64_t Sd[14 * SJ];     // dup-pair S: 9.1 KB
    __shared__ __align__(16) float w0s[126 * 16];      // [k][16 o]: 8 KB

    const int m   = blockIdx.x;
    const int og  = blockIdx.y;          // 0..5
    const int tid = threadIdx.x;

    // ── Phase A: stage inputs (independent loads, one sync) ──
    for (int t = tid; t < 24 * XP; t += 224) xp[t] = 0.0f;
    for (int t = tid; t < 24 * 28; t += 224) w1s[t] = w1[t];
    // w0 transposed, k-major reads (coalesced): w0s[k*16+ol] = w0[(og*16+ol)*126+k]
    for (int t = tid; t < 126 * 16; t += 224) {
        const int k = t % 126, ol = t / 126;
        w0s[k * 16 + ol] = w0[(og * 16 + ol) * 126 + k];
    }
    __syncthreads();   // xp zeros visible before interior writes
    // x slice: 24 rows × 56, vectorized float4 (aligned: 3136%4==0, 56%4==0)
    {
        const float4* __restrict__ x4 = reinterpret_cast<const float4*>(x + m * 56);
        for (int t = tid; t < 24 * 14; t += 224) {
            const int i = t / 14, c = t % 14;
            const float4 v = x4[i * 784 + c];
            float* dst = &xp[i * XP + 5 + c * 4];
            dst[0] = v.x; dst[1] = v.y; dst[2] = v.z; dst[3] = v.w;
        }
    }
    __syncthreads();

    // ── Phase B: build S slice (14 j × 73 r) into Sd ──
    for (int it = tid; it < 14 * 73; it += 224) {
        const int j = it / 73;
        const int r = it % 73;
        float a0 = 0.f, a1 = 0.f, a2 = 0.f, a3 = 0.f;
        if (r < 64) {
            #pragma unroll
            for (int i = 0; i < 24; i += 2) {
                a0 = fmaf(xp[i * XP + r + 1],     w1s[i * 28 + j],          a0);
                a1 = fmaf(xp[i * XP + r],         w1s[i * 28 + 14 + j],     a1);
                a2 = fmaf(xp[(i+1) * XP + r + 1], w1s[(i+1) * 28 + j],      a2);
                a3 = fmaf(xp[(i+1) * XP + r],     w1s[(i+1) * 28 + 14 + j], a3);
            }
        } else {
            const int kh = r - 64;
            if (kh >= 4) {
                #pragma unroll
                for (int i = 0; i < 24; i += 2) {
                    a0 = fmaf(xp[i * XP + kh + 1],     w1s[i * 28 + j],     a0);
                    a2 = fmaf(xp[(i+1) * XP + kh + 1], w1s[(i+1) * 28 + j], a2);
                }
            }
            if (kh <= 4) {
                #pragma unroll
                for (int i = 0; i < 24; i += 2) {
                    a1 = fmaf(xp[i * XP + kh + 56],     w1s[i * 28 + 14 + j],     a1);
                    a3 = fmaf(xp[(i+1) * XP + kh + 56], w1s[(i+1) * 28 + 14 + j], a3);
                }
            }
        }
        Sd[j * SJ + r] = pack2((a0 + a2) + (a1 + a3));
    }
    __syncthreads();

    // ── Phase C: contraction ──
    const int ow = tid & 3;                  // 4 o's each
    const int n  = tid >> 2;                 // 0..55
    const int rbase = (n == 0) ? 64 : n;

    const uint64_t* __restrict__ sp = Sd + rbase;
    const ulonglong2* __restrict__ wp =
        reinterpret_cast<const ulonglong2*>(w0s) + ow;   // [k*4]: row = 4 ulonglong2

    uint64_t acc0 = 0, acc1 = 0;
    #pragma unroll
    for (int j = 0; j < 14; j++) {
        uint64_t svd[9];
        #pragma unroll
        for (int kh = 0; kh < 9; kh++)           // 9 independent LDS.64, batched
            svd[kh] = sp[j * SJ + kh];
        #pragma unroll
        for (int kh = 0; kh < 9; kh++) {
            const ulonglong2 wv = wp[(kh * 14 + j) * 4];
            ffma2(acc0, wv.x, svd[kh]);
            ffma2(acc1, wv.y, svd[kh]);
        }
    }

    const int ob = og * 16 + ow * 4;
    float* op = out + m * 56 + n;
    float2 r;
    r = unpack2(acc0); op[(ob + 0) * 3136] = r.x; op[(ob + 1) * 3136] = r.y;
    r = unpack2(acc1); op[(ob + 2) * 3136] = r.x; op[(ob + 3) * 3136] = r.y;
}

extern "C" void kernel_launch(void* const* d_in, const int* in_sizes, int n_in,
                              void* d_out, int out_size)
{
    const float* x = (const float*)d_in[0];
    const float* w0;
    const float* w1;
    if (in_sizes[1] == 12096) { w0 = (const float*)d_in[1]; w1 = (const float*)d_in[2]; }
    else                      { w0 = (const float*)d_in[2]; w1 = (const float*)d_in[1]; }
    float* out = (float*)d_out;

    fused_kernel<<<dim3(56, 6), 224>>>(x, w0, w1, out);
}

// round 9
// speedup vs baseline: 1.2003x; 1.2003x over previous
#include <cuda_runtime.h>
#include <cstdint>

// out[o,m,n] = sum_{kh,j} w0[o,kh,j] * S[m, n+kh, j]       (n >= 1)
// out[o,m,0] = sum_{kh,j} w0[o,kh,j] * S0[m, kh, j]
// Scratch: Sg[((m*14 + j)*80) + r], r in [0,63] = S rows, [64,72] = S0 rows.

__device__ __align__(16) float Sg[56 * 14 * 80];

__device__ __forceinline__ uint64_t pack2(float s) {
    uint64_t r;
    unsigned u = __float_as_uint(s);
    asm("mov.b64 %0, {%1, %1};" : "=l"(r) : "r"(u));
    return r;
}
__device__ __forceinline__ void ffma2(uint64_t& d, uint64_t a, uint64_t b) {
    asm("fma.rn.f32x2 %0, %1, %2, %0;" : "+l"(d) : "l"(a), "l"(b));
}
__device__ __forceinline__ void addf2(uint64_t& d, uint64_t a) {
    asm("add.rn.f32x2 %0, %0, %1;" : "+l"(d) : "l"(a));
}
__device__ __forceinline__ float2 unpack2(uint64_t v) {
    unsigned lo, hi;
    asm("mov.b64 {%0, %1}, %2;" : "=r"(lo), "=r"(hi) : "l"(v));
    return make_float2(__uint_as_float(lo), __uint_as_float(hi));
}

// ───────────── Kernel 1: build S ─────────────
#define XP 68
__global__ __launch_bounds__(160)
void build_S_kernel(const float* __restrict__ x, const float* __restrict__ w1)
{
    __shared__ float xp[24 * XP];   // xp[i][h+5] = x[i,m,h], pads zero
    __shared__ float w1s[24 * 28];
    const int m = blockIdx.x, jg = blockIdx.y, tid = threadIdx.x;

    for (int t = tid; t < 24 * XP; t += 160) xp[t] = 0.0f;
    for (int t = tid; t < 24 * 28; t += 160) w1s[t] = w1[t];
    __syncthreads();
    for (int t = tid; t < 24 * 56; t += 160) {
        const int i = t / 56, h = t % 56;
        xp[i * XP + 5 + h] = x[i * 3136 + m * 56 + h];
    }
    __syncthreads();

    if (tid < 146) {
        const int j = jg * 2 + tid / 73;
        const int r = tid % 73;
        float a0 = 0.f, a1 = 0.f, a2 = 0.f, a3 = 0.f;
        if (r < 64) {
            #pragma unroll
            for (int i = 0; i < 24; i += 2) {
                a0 = fmaf(xp[i * XP + r + 1],     w1s[i * 28 + j],          a0);
                a1 = fmaf(xp[i * XP + r],         w1s[i * 28 + 14 + j],     a1);
                a2 = fmaf(xp[(i+1) * XP + r + 1], w1s[(i+1) * 28 + j],      a2);
                a3 = fmaf(xp[(i+1) * XP + r],     w1s[(i+1) * 28 + 14 + j], a3);
            }
        } else {
            const int kh = r - 64;
            if (kh >= 4) {
                #pragma unroll
                for (int i = 0; i < 24; i += 2) {
                    a0 = fmaf(xp[i * XP + kh + 1],     w1s[i * 28 + j],     a0);
                    a2 = fmaf(xp[(i+1) * XP + kh + 1], w1s[(i+1) * 28 + j], a2);
                }
            }
            if (kh <= 4) {
                #pragma unroll
                for (int i = 0; i < 24; i += 2) {
                    a1 = fmaf(xp[i * XP + kh + 56],     w1s[i * 28 + 14 + j],     a1);
                    a3 = fmaf(xp[(i+1) * XP + kh + 56], w1s[(i+1) * 28 + 14 + j], a3);
                }
            }
        }
        Sg[(m * 14 + j) * 80 + r] = (a0 + a2) + (a1 + a3);
    }
}

// ───────────── Kernel 2: register-tiled contraction ─────────────
// grid (56 m, 6 og of 16 o), block 336 = ks(3) × np(28) × ow(4).
// Thread: 4 o × 2 n, 42 k (its ks third). ILP = 4 indep FFMA2 chains.
// k = ks*42 + t, 42 % 14 == 0 -> j = t%14 (compile-time), kh = ks*3 + t/14 (affine).
__global__ __launch_bounds__(336, 2)
void contract_kernel(const float* __restrict__ w0, float* __restrict__ out)
{
    __shared__ __align__(16) uint64_t Sd[14 * 80];     // dup-pair S: 8.75 KB
    __shared__ __align__(16) float w0s[126 * 16];      // [k][16 o]: 8 KB
    __shared__ __align__(16) uint64_t red[224 * 4];    // ks partials: 7 KB

    const int m   = blockIdx.x;
    const int og  = blockIdx.y;
    const int tid = threadIdx.x;

    // stage S (coalesced f32 reads -> dup-pair u64)
    for (int t = tid; t < 1120; t += 336)
        Sd[t] = pack2(Sg[m * 1120 + t]);
    // stage w0 transposed, k-major reads (coalesced)
    for (int t = tid; t < 2016; t += 336) {
        const int k = t % 126, ol = t / 126;
        w0s[k * 16 + ol] = w0[(og * 16 + ol) * 126 + k];
    }
    __syncthreads();

    const int ks = tid / 112;            // 0..2
    const int rr = tid % 112;
    const int np = rr >> 2;              // 0..27 (n pair)
    const int ow = rr & 3;               // 0..3 (o quad)
    const int sb0 = (np == 0) ? 64 : 2 * np;   // n=0 -> S0 rows 64..72
    const int sb1 = 2 * np + 1;
    const int kh0 = ks * 3;

    const uint64_t* __restrict__ sp0 = Sd + kh0 + sb0;
    const uint64_t* __restrict__ sp1 = Sd + kh0 + sb1;
    const float*    __restrict__ wp  = w0s + ks * 42 * 16 + ow * 4;

    uint64_t aA0 = 0, aA1 = 0, aB0 = 0, aB1 = 0;
    #pragma unroll
    for (int t = 0; t < 42; t++) {
        const int off = (t % 14) * 80 + (t / 14);        // compile-time
        const uint64_t s0 = sp0[off];
        const uint64_t s1 = sp1[off];
        const ulonglong2 wv = *reinterpret_cast<const ulonglong2*>(wp + t * 16);
        ffma2(aA0, wv.x, s0);  ffma2(aA1, wv.y, s0);
        ffma2(aB0, wv.x, s1);  ffma2(aB1, wv.y, s1);
    }

    if (ks > 0) {
        ulonglong2* dst = reinterpret_cast<ulonglong2*>(&red[((ks - 1) * 112 + rr) * 4]);
        dst[0] = make_ulonglong2(aA0, aA1);
        dst[1] = make_ulonglong2(aB0, aB1);
    }
    __syncthreads();

    if (ks == 0) {
        #pragma unroll
        for (int s = 0; s < 2; s++) {
            const ulonglong2* src =
                reinterpret_cast<const ulonglong2*>(&red[(s * 112 + rr) * 4]);
            const ulonglong2 p0 = src[0], p1 = src[1];
            addf2(aA0, p0.x);  addf2(aA1, p0.y);
            addf2(aB0, p1.x);  addf2(aB1, p1.y);
        }
        const int ob = og * 16 + ow * 4;
        const int n0 = 2 * np;                    // np==0: stores n=0 (patched) and n=1
        float* op = out + m * 56 + n0;
        const float2 A0 = unpack2(aA0), A1 = unpack2(aA1);
        const float2 B0 = unpack2(aB0), B1 = unpack2(aB1);
        *reinterpret_cast<float2*>(op + (ob + 0) * 3136) = make_float2(A0.x, B0.x);
        *reinterpret_cast<float2*>(op + (ob + 1) * 3136) = make_float2(A0.y, B0.y);
        *reinterpret_cast<float2*>(op + (ob + 2) * 3136) = make_float2(A1.x, B1.x);
        *reinterpret_cast<float2*>(op + (ob + 3) * 3136) = make_float2(A1.y, B1.y);
    }
}

extern "C" void kernel_launch(void* const* d_in, const int* in_sizes, int n_in,
                              void* d_out, int out_size)
{
    const float* x = (const float*)d_in[0];
    const float* w0;
    const float* w1;
    if (in_sizes[1] == 12096) { w0 = (const float*)d_in[1]; w1 = (const float*)d_in[2]; }
    else                      { w0 = (const float*)d_in[2]; w1 = (const float*)d_in[1]; }
    float* out = (float*)d_out;

    build_S_kernel<<<dim3(56, 7), 160>>>(x, w1);
    contract_kernel<<<dim3(56, 6), 336>>>(w0, out);
}